// round 5
// baseline (speedup 1.0000x reference)
#include <cuda_runtime.h>
#include <cstdint>

// Problem constants (from reference_code)
#define DD    14
#define KK    2
#define BB    512
#define FF    512
#define NT    512
#define NF    1024
#define CELLS (BB * FF)          // 262144 (b,f) cells
#define PIX   (DD * DD)          // 196 pixels per cell
#define CPB   32                 // cells per block
#define THREADS 256
#define STRIDEW 57               // words per cell table (odd -> conflict-free STS)
// flat layout per cell: [0..13]=ex0 [14..27]=ex1 [28..41]=ey0 [42..55]=ey1 [56]=pad

__device__ __forceinline__ float ex2(float a) {
    float r;
    asm("ex2.approx.ftz.f32 %0, %1;" : "=f"(r) : "f"(a));
    return r;
}

// Block handles 32 consecutive (b,f) cells.
// Phase 1 (threads 0..63): thread (axis, cell) builds the 14-entry separable
//   exp tables for both spots via an incremental recurrence in log2 space
//   (constant 2nd difference: 2 FADD + EX2 per entry), SoA layout in smem.
// Phase 2 (8 warps x 4 cells): each warp pulls the full 56-word table into
//   registers with TWO conflict-free LDS.32, then distributes values per
//   pixel-pair with shfl.idx (register crossbar - off the L1tex pipe).
//   Stores are contiguous float2 per lane (coalesced).
__global__ __launch_bounds__(THREADS) void gaussian_spot_kernel(
    const float* __restrict__ height,      // [K,B,F]
    const float* __restrict__ width,       // [K,B,F]
    const float* __restrict__ x,           // [K,B,F]
    const float* __restrict__ y,           // [K,B,F]
    const float* __restrict__ background,  // [B,F]
    const float* __restrict__ target_locs, // [NT,NF,2]
    const int*   __restrict__ n_idx,       // [B,1]
    const int*   __restrict__ f_arr,       // [F]
    float*       __restrict__ out)         // [1,B,F,D,D]
{
    __shared__ float tabf[CPB * STRIDEW + 8];   // +8 pad: lanes 28..31 over-read
    __shared__ float bgs[CPB];

    const int t = threadIdx.x;
    const int blockbase = blockIdx.x * CPB;

    // ---------------- Phase 1: build tables (threads 0..63) ----------------
    if (t < 2 * CPB) {
        const int lc   = t & (CPB - 1);
        const int axis = t >> 5;          // 0 = x/i-axis (ex), 1 = y/j-axis (ey)
        const int cell = blockbase + lc;
        const int b = cell >> 9;          // / FF
        const int f = cell & (FF - 1);

        const int n  = n_idx[b];          // broadcast within block
        const int fi = f_arr[f];          // coalesced
        const float cloc = target_locs[((size_t)n * NF + (size_t)fi) * 2 + axis];
        if (axis == 0) bgs[lc] = background[cell];   // coalesced

        float a[KK], dl[KK], e2[KK];
#pragma unroll
        for (int k = 0; k < KK; k++) {
            const int off = k * CELLS + cell;        // coalesced loads
            const float h  = height[off];
            const float w  = width[off];
            const float sh = axis ? y[off] : x[off];
            const float c  = cloc + sh;              // spot center on this axis
            const float w2    = w * w;
            const float invw2 = __fdividef(1.0f, w2);
            const float s2    = 0.72134752044f * invw2;   // log2e / (2 w^2)
            const float lp2 = axis ? 0.0f
                                   : __log2f(h * 0.15915494309f * invw2);
            a[k]  = fmaf(-c * c, s2, lp2);           // a(0)
            dl[k] = (c + c - 1.0f) * s2;             // a(1)-a(0)
            e2[k] = s2 + s2;                         // -(2nd difference)
        }

        // SoA: spot0 at +axis*28, spot1 at +axis*28+14. Word stride 57 is odd
        // -> banks (25*lc + c) % 32 distinct across lanes: conflict-free STS.32.
        float* trow = tabf + lc * STRIDEW + axis * 28;
#pragma unroll
        for (int d = 0; d < DD; d++) {
            trow[d]      = ex2(a[0]);
            trow[14 + d] = ex2(a[1]);
            a[0] += dl[0]; dl[0] -= e2[0];
            a[1] += dl[1]; dl[1] -= e2[1];
        }
    }
    __syncthreads();

    // ---------------- Phase 2: emit pixels (8 warps x 4 cells each) --------
    const int warp = t >> 5;
    const int lane = t & 31;

    // Pixel-pair p = r*32+lane -> row i = p/7, col j = 2*(p%7). Hoisted.
    int ir[4], jr[4];
#pragma unroll
    for (int r = 0; r < 4; r++) {
        const int p  = r * 32 + lane;
        const int pp = (p < 98) ? p : 97;   // clamp for safe shfl indices
        ir[r] = pp / 7;
        jr[r] = (pp - ir[r] * 7) * 2;
    }

#pragma unroll
    for (int cc = 0; cc < 4; cc++) {
        const int lc = warp * 4 + cc;
        const float* cf = tabf + lc * STRIDEW;
        // Register-resident table: lane l holds flat[l] and flat[28+l].
        // regA: ex0[0..13] (lanes 0-13), ex1[0..13] (lanes 14-27)
        // regB: ey0[0..13] (lanes 0-13), ey1[0..13] (lanes 14-27)
        const float regA = cf[lane];            // 1 conflict-free LDS.32
        const float regB = cf[28 + lane];       // 1 conflict-free LDS.32
        const float bg   = bgs[lc];
        float* outp = out + (size_t)(blockbase + lc) * PIX;

#pragma unroll
        for (int r = 0; r < 4; r++) {
            const float ex0  = __shfl_sync(0xffffffffu, regA, ir[r]);
            const float ex1  = __shfl_sync(0xffffffffu, regA, ir[r] + 14);
            const float ey00 = __shfl_sync(0xffffffffu, regB, jr[r]);
            const float ey01 = __shfl_sync(0xffffffffu, regB, jr[r] + 1);
            const float ey10 = __shfl_sync(0xffffffffu, regB, jr[r] + 14);
            const float ey11 = __shfl_sync(0xffffffffu, regB, jr[r] + 15);

            float v0 = fmaf(ex1, ey10, bg);
            v0       = fmaf(ex0, ey00, v0);
            float v1 = fmaf(ex1, ey11, bg);
            v1       = fmaf(ex0, ey01, v1);

            const int p = r * 32 + lane;
            if (p < 98)
                *reinterpret_cast<float2*>(outp + 2 * p) = make_float2(v0, v1);
        }
    }
}

extern "C" void kernel_launch(void* const* d_in, const int* in_sizes, int n_in,
                              void* d_out, int out_size)
{
    const float* height      = (const float*)d_in[0];
    const float* width       = (const float*)d_in[1];
    const float* x           = (const float*)d_in[2];
    const float* y           = (const float*)d_in[3];
    const float* background  = (const float*)d_in[4];
    const float* target_locs = (const float*)d_in[5];
    const int*   n_idx       = (const int*)d_in[6];
    const int*   f_arr       = (const int*)d_in[7];
    float*       out         = (float*)d_out;

    const int blocks = CELLS / CPB;   // 8192
    gaussian_spot_kernel<<<blocks, THREADS>>>(height, width, x, y, background,
                                              target_locs, n_idx, f_arr, out);
}

// round 6
// speedup vs baseline: 1.1710x; 1.1710x over previous
#include <cuda_runtime.h>
#include <cstdint>

// Problem constants (from reference_code)
#define DD    14
#define KK    2
#define BB    512
#define FF    512
#define NT    512
#define NF    1024
#define CELLS (BB * FF)          // 262144 (b,f) cells
#define PIX   (DD * DD)          // 196 pixels per cell
#define CPB   32                 // cells per block
#define THREADS 256
#define STRIDE 34                // float2 per cell: cex[0..15] cey[16..31] pad[2]
                                 // 34*8=272B = 16*17 -> per-cell bases 16B-aligned

__device__ __forceinline__ float ex2(float a) {
    float r;
    asm("ex2.approx.ftz.f32 %0, %1;" : "=f"(r) : "f"(a));
    return r;
}

// Block handles 32 consecutive (b,f) cells.
// Phase 1 (threads 0..63): thread (axis, cell) builds the 14-entry separable
//   exp tables for both spots via an incremental log2-space recurrence
//   (constant 2nd difference: 2 FADD + EX2 per entry). tab[d] = {spot0, spot1},
//   h/(2*pi*w^2) folded into the x-axis table.
// Phase 2 (8 warps x 4 cells): ROW-PARALLEL lanes. lane l<28 -> (ri=l/7, jp=l%7)
//   owns pixel columns (2jp, 2jp+1) on rows 4r+ri. Its ey values are round-
//   invariant: ONE aligned LDS.128 preloads them. Each round: 1 broadcast
//   LDS.64 (ex pair), 4 FMA, 1 coalesced STG.64.
__global__ __launch_bounds__(THREADS) void gaussian_spot_kernel(
    const float* __restrict__ height,      // [K,B,F]
    const float* __restrict__ width,       // [K,B,F]
    const float* __restrict__ x,           // [K,B,F]
    const float* __restrict__ y,           // [K,B,F]
    const float* __restrict__ background,  // [B,F]
    const float* __restrict__ target_locs, // [NT,NF,2]
    const int*   __restrict__ n_idx,       // [B,1]
    const int*   __restrict__ f_arr,       // [F]
    float*       __restrict__ out)         // [1,B,F,D,D]
{
    __shared__ __align__(16) float2 tab[CPB * STRIDE];
    __shared__ float bgs[CPB];

    const int t = threadIdx.x;
    const int blockbase = blockIdx.x * CPB;

    // ---------------- Phase 1: build tables (threads 0..63) ----------------
    if (t < 2 * CPB) {
        const int lc   = t & (CPB - 1);
        const int axis = t >> 5;          // 0 = x/i-axis (ex), 1 = y/j-axis (ey)
        const int cell = blockbase + lc;
        const int b = cell >> 9;          // / FF
        const int f = cell & (FF - 1);

        const int n  = n_idx[b];          // broadcast within block
        const int fi = f_arr[f];          // coalesced
        const float cloc = target_locs[((size_t)n * NF + (size_t)fi) * 2 + axis];
        if (axis == 0) bgs[lc] = background[cell];   // coalesced

        float a[KK], dl[KK], e2[KK];
#pragma unroll
        for (int k = 0; k < KK; k++) {
            const int off = k * CELLS + cell;        // coalesced loads
            const float h  = height[off];
            const float w  = width[off];
            const float sh = axis ? y[off] : x[off];
            const float c  = cloc + sh;              // spot center on this axis
            const float w2    = w * w;
            const float invw2 = __fdividef(1.0f, w2);
            const float s2    = 0.72134752044f * invw2;   // log2e / (2 w^2)
            const float lp2 = axis ? 0.0f
                                   : __log2f(h * 0.15915494309f * invw2);
            a[k]  = fmaf(-c * c, s2, lp2);           // a(0)
            dl[k] = (c + c - 1.0f) * s2;             // a(1)-a(0)
            e2[k] = s2 + s2;                         // -(2nd difference)
        }

        float2* trow = tab + lc * STRIDE + axis * 16;
#pragma unroll
        for (int d = 0; d < DD; d++) {
            trow[d] = make_float2(ex2(a[0]), ex2(a[1]));
            a[0] += dl[0]; dl[0] -= e2[0];
            a[1] += dl[1]; dl[1] -= e2[1];
        }
    }
    __syncthreads();

    // ---------------- Phase 2: emit pixels (8 warps x 4 cells each) --------
    const int warp = t >> 5;
    const int lane = t & 31;

    const bool active = lane < 28;
    const int  ls = active ? lane : 0;    // clamp idle lanes to safe indices
    const int  ri = ls / 7;               // row-subgroup 0..3
    const int  jp = ls - ri * 7;          // pair column 0..6

#pragma unroll
    for (int cc = 0; cc < 4; cc++) {
        const int lc = warp * 4 + cc;
        const float2* cex = tab + lc * STRIDE;   // ex[i] (prefactor folded)
        const float2* cey = cex + 16;            // ey[j]

        // Round-invariant ey preload: cey[2jp], cey[2jp+1] in one LDS.128.
        // eyq = {ey0[2jp], ey1[2jp], ey0[2jp+1], ey1[2jp+1]}
        const float4 eyq = *reinterpret_cast<const float4*>(cey + 2 * jp);
        const float  bg  = bgs[lc];
        float* outp = out + (size_t)(blockbase + lc) * PIX;

#pragma unroll
        for (int r = 0; r < 4; r++) {
            const int row = 4 * r + ri;               // 0..15 (14,15 masked)
            const float2 exv = cex[(row < DD) ? row : 0];  // broadcast LDS.64
            float v0 = fmaf(exv.y, eyq.y, bg);
            v0       = fmaf(exv.x, eyq.x, v0);
            float v1 = fmaf(exv.y, eyq.w, bg);
            v1       = fmaf(exv.x, eyq.z, v1);
            if (active && row < DD)
                *reinterpret_cast<float2*>(outp + row * DD + 2 * jp)
                    = make_float2(v0, v1);
        }
    }
}

extern "C" void kernel_launch(void* const* d_in, const int* in_sizes, int n_in,
                              void* d_out, int out_size)
{
    const float* height      = (const float*)d_in[0];
    const float* width       = (const float*)d_in[1];
    const float* x           = (const float*)d_in[2];
    const float* y           = (const float*)d_in[3];
    const float* background  = (const float*)d_in[4];
    const float* target_locs = (const float*)d_in[5];
    const int*   n_idx       = (const int*)d_in[6];
    const int*   f_arr       = (const int*)d_in[7];
    float*       out         = (float*)d_out;

    const int blocks = CELLS / CPB;   // 8192
    gaussian_spot_kernel<<<blocks, THREADS>>>(height, width, x, y, background,
                                              target_locs, n_idx, f_arr, out);
}

// round 7
// speedup vs baseline: 1.2200x; 1.0419x over previous
#include <cuda_runtime.h>
#include <cstdint>

// Problem constants (from reference_code)
#define DD    14
#define KK    2
#define BB    512
#define FF    512
#define NT    512
#define NF    1024
#define CELLS (BB * FF)          // 262144 (b,f) cells
#define PIX   (DD * DD)          // 196 pixels per cell
#define CPB   32                 // cells per block
#define THREADS 256
#define STRIDE 34                // float2 per cell: cex[0..15] cey[16..31] pad[2]
                                 // = 17 x 16B chunks; 17 odd -> conflict-free 128b ops

__device__ __forceinline__ float ex2(float a) {
    float r;
    asm("ex2.approx.ftz.f32 %0, %1;" : "=f"(r) : "f"(a));
    return r;
}

// Block handles 32 consecutive (b,f) cells.
// Phase 1 (threads 0..127): thread (hf, axis, cell) builds 8 entries of the
//   14-entry separable exp table (d in [8*hf, 8*hf+8), last 2 masked for hf=1)
//   for both spots via an incremental log2-space recurrence started at d0.
//   Entries are written PAIRWISE as STS.128 -> conflict-free (stride 17 chunks).
// Phase 2 (8 warps x 4 cells): ROW-PARALLEL lanes. lane l<28 -> (ri=l/7, jp=l%7)
//   owns pixel columns (2jp, 2jp+1) on rows 4r+ri. ey values are round-invariant
//   (ONE aligned LDS.128); each round: 1 broadcast LDS.64 + 4 FMA + coalesced STG.64.
__global__ __launch_bounds__(THREADS, 7) void gaussian_spot_kernel(
    const float* __restrict__ height,      // [K,B,F]
    const float* __restrict__ width,       // [K,B,F]
    const float* __restrict__ x,           // [K,B,F]
    const float* __restrict__ y,           // [K,B,F]
    const float* __restrict__ background,  // [B,F]
    const float* __restrict__ target_locs, // [NT,NF,2]
    const int*   __restrict__ n_idx,       // [B,1]
    const int*   __restrict__ f_arr,       // [F]
    float*       __restrict__ out)         // [1,B,F,D,D]
{
    __shared__ __align__(16) float2 tab[CPB * STRIDE];
    __shared__ float bgs[CPB];

    const int t = threadIdx.x;
    const int blockbase = blockIdx.x * CPB;

    // ---------------- Phase 1: build tables (threads 0..127) ---------------
    if (t < 4 * CPB) {
        const int lc   = t & (CPB - 1);
        const int axis = (t >> 5) & 1;    // 0 = x/i-axis (ex), 1 = y/j-axis (ey)
        const int hf   = t >> 6;          // 0: d=0..7, 1: d=8..13 (+2 masked)
        const int cell = blockbase + lc;
        const int b = cell >> 9;          // / FF
        const int f = cell & (FF - 1);

        const int n  = n_idx[b];          // broadcast within block
        const int fi = f_arr[f];          // coalesced
        const float cloc = target_locs[((size_t)n * NF + (size_t)fi) * 2 + axis];
        if ((t >> 5) == 0) bgs[lc] = background[cell];   // coalesced, once

        const float d0 = (float)(hf << 3);

        float a[KK], dl[KK], e2[KK];
#pragma unroll
        for (int k = 0; k < KK; k++) {
            const int off = k * CELLS + cell;        // coalesced loads
            const float h  = height[off];
            const float w  = width[off];
            const float sh = axis ? y[off] : x[off];
            const float c  = cloc + sh;              // spot center on this axis
            const float w2    = w * w;
            const float invw2 = __fdividef(1.0f, w2);
            const float s2    = 0.72134752044f * invw2;   // log2e / (2 w^2)
            const float lp2 = axis ? 0.0f
                                   : __log2f(h * 0.15915494309f * invw2);
            const float dc = d0 - c;
            a[k]  = fmaf(-dc, dc * s2, lp2);         // a(d0)
            dl[k] = -(dc + dc + 1.0f) * s2;          // a(d0+1)-a(d0)
            e2[k] = s2 + s2;                         // -(2nd difference)
        }

        float2* trow = tab + lc * STRIDE + axis * 16 + (hf << 3);
#pragma unroll
        for (int dd = 0; dd < 8; dd += 2) {
            const float e00 = ex2(a[0]);
            const float e01 = ex2(a[1]);
            a[0] += dl[0]; dl[0] -= e2[0];
            a[1] += dl[1]; dl[1] -= e2[1];
            const float e10 = ex2(a[0]);
            const float e11 = ex2(a[1]);
            a[0] += dl[0]; dl[0] -= e2[0];
            a[1] += dl[1]; dl[1] -= e2[1];
            if ((hf << 3) + dd < DD)   // masks d=14,15 for hf=1
                *reinterpret_cast<float4*>(trow + dd)
                    = make_float4(e00, e01, e10, e11);   // conflict-free STS.128
        }
    }
    __syncthreads();

    // ---------------- Phase 2: emit pixels (8 warps x 4 cells each) --------
    const int warp = t >> 5;
    const int lane = t & 31;

    const bool active = lane < 28;
    const int  ls = active ? lane : 0;    // clamp idle lanes to safe indices
    const int  ri = ls / 7;               // row-subgroup 0..3
    const int  jp = ls - ri * 7;          // pair column 0..6

#pragma unroll
    for (int cc = 0; cc < 4; cc++) {
        const int lc = warp * 4 + cc;
        const float2* cex = tab + lc * STRIDE;   // ex[i] (prefactor folded)
        const float2* cey = cex + 16;            // ey[j]

        // Round-invariant ey preload: cey[2jp], cey[2jp+1] in one LDS.128.
        // eyq = {ey0[2jp], ey1[2jp], ey0[2jp+1], ey1[2jp+1]}
        const float4 eyq = *reinterpret_cast<const float4*>(cey + 2 * jp);
        const float  bg  = bgs[lc];
        float* outp = out + (size_t)(blockbase + lc) * PIX;

#pragma unroll
        for (int r = 0; r < 4; r++) {
            const int row = 4 * r + ri;               // 0..15 (14,15 masked)
            const float2 exv = cex[(row < DD) ? row : 0];  // broadcast LDS.64
            float v0 = fmaf(exv.y, eyq.y, bg);
            v0       = fmaf(exv.x, eyq.x, v0);
            float v1 = fmaf(exv.y, eyq.w, bg);
            v1       = fmaf(exv.x, eyq.z, v1);
            if (active && row < DD)
                *reinterpret_cast<float2*>(outp + row * DD + 2 * jp)
                    = make_float2(v0, v1);
        }
    }
}

extern "C" void kernel_launch(void* const* d_in, const int* in_sizes, int n_in,
                              void* d_out, int out_size)
{
    const float* height      = (const float*)d_in[0];
    const float* width       = (const float*)d_in[1];
    const float* x           = (const float*)d_in[2];
    const float* y           = (const float*)d_in[3];
    const float* background  = (const float*)d_in[4];
    const float* target_locs = (const float*)d_in[5];
    const int*   n_idx       = (const int*)d_in[6];
    const int*   f_arr       = (const int*)d_in[7];
    float*       out         = (float*)d_out;

    const int blocks = CELLS / CPB;   // 8192
    gaussian_spot_kernel<<<blocks, THREADS>>>(height, width, x, y, background,
                                              target_locs, n_idx, f_arr, out);
}